// round 17
// baseline (speedup 1.0000x reference)
#include <cuda_runtime.h>

#define BB 2
#define DD 64
#define HH 128
#define WW 128
#define NS (BB*DD)      // 128 slices
#define QPS 4           // quarters per slice (both kernels)
#define NBLK1 (NS*QPS)  // 512 pack blocks, 32 rows each
#define NT1 256
#define NBLK2 (NS*QPS)  // 512 walk blocks, 128 word-tasks each
#define NT2 128
#define GROW 148        // stored rows per slice: 10 guard + 128 + 10 guard
#define GSTR 8          // words per stored row: [g0, W0..W3, g5, pad, pad]

constexpr int count_tab() {
    int n = 0;
    for (int dr = -9; dr <= 9; ++dr)
        for (int dc = -9; dc <= 9; ++dc) {
            int d2 = dr * dr + dc * dc;
            if (d2 >= 1 && d2 <= 99) ++n;
        }
    return n;
}
constexpr int TABN = count_tab();           // 304
constexpr int count_groups() {
    int n = 0;
    for (int d2 = 1; d2 <= 99; ++d2) {
        bool any = false;
        for (int dr = -9; dr <= 9 && !any; ++dr)
            for (int dc = -9; dc <= 9; ++dc)
                if (dr * dr + dc * dc == d2) { any = true; break; }
        if (any) ++n;
    }
    return n;
}
constexpr int NG = count_groups();
constexpr int NBATCH = (NG + 3) / 4;

constexpr double csqrt_(double x) {
    double g = x > 1.0 ? x : 1.0;
    for (int i = 0; i < 60; ++i) g = 0.5 * (g + x / g);
    return g;
}
struct OffTab {
    signed char dr[TABN], dc[TABN];
    short gstart[NG], gcnt[NG];
    float sv[NG];
};
constexpr OffTab make_tab() {
    OffTab t{};
    int n = 0, gi = 0;
    for (int d2 = 1; d2 <= 99; ++d2) {
        int start = n;
        for (int dr = -9; dr <= 9; ++dr)
            for (int dc = -9; dc <= 9; ++dc)
                if (dr * dr + dc * dc == d2) {
                    t.dr[n] = (signed char)dr; t.dc[n] = (signed char)dc; ++n;
                }
        if (n > start) {
            t.gstart[gi] = (short)start;
            t.gcnt[gi]   = (short)(n - start);
            t.sv[gi]     = (float)csqrt_((double)d2);
            ++gi;
        }
    }
    return t;
}
__device__ constexpr OffTab TB = make_tab();

// packed planes (static zero-init provides all guards; guard cells are never
// written, so they stay zero across graph replays)
__device__ unsigned gS[NS][GROW][GSTR];     // thresholded y_pred bits
__device__ unsigned gY[NS][HH][4];          // y_true != 0 bits
__device__ int      gFG[NBLK1];             // per-(slice,quarter) fg flag
__device__ volatile float g_psum[NBLK2];
__device__ volatile float g_pcnt[NBLK2];
__device__ unsigned g_done = 0;

// compress 8 nibbles (low 4 bits of each byte) into a 32-bit word,
// preserving pixel order: result bit (4j+i) = bit i of byte j.
__device__ __forceinline__ unsigned nib_compress(unsigned long long x) {
    x = (x | (x >> 4))  & 0x00FF00FF00FF00FFull;
    x = (x | (x >> 8))  & 0x0000FFFF0000FFFFull;
    x = (x | (x >> 16));
    return (unsigned)x;
}

// ---------------- kernel 1: pack (pure streaming read) ----------------
__global__ __launch_bounds__(NT1)
void pack_kernel(const float* __restrict__ yp, const float* __restrict__ yt)
{
    __shared__ unsigned char pS[32][32];
    __shared__ unsigned char pY[32][32];

    const int blk   = blockIdx.x;
    const int slice = blk >> 2;
    const int R0    = (blk & 3) * 32;
    const int t     = threadIdx.x;
    const int lane  = t & 31, wp = t >> 5;
    const float* yps = yp + (size_t)slice * HH * WW;
    const float* yts = yt + (size_t)slice * HH * WW;

    // MLP-8 float4 loads: warp wp owns rows R0 + wp*4 + {0..3}
    float4 a[4], b[4];
    #pragma unroll
    for (int i = 0; i < 4; ++i)
        a[i] = __ldg((const float4*)(yps + (size_t)(R0 + wp * 4 + i) * WW) + lane);
    #pragma unroll
    for (int i = 0; i < 4; ++i)
        b[i] = __ldg((const float4*)(yts + (size_t)(R0 + wp * 4 + i) * WW) + lane);
    #pragma unroll
    for (int i = 0; i < 4; ++i) {
        unsigned n = (a[i].x > 0.7f ? 1u : 0u) | (a[i].y > 0.7f ? 2u : 0u)
                   | (a[i].z > 0.7f ? 4u : 0u) | (a[i].w > 0.7f ? 8u : 0u);
        pS[wp * 4 + i][lane] = (unsigned char)n;
        unsigned m = (b[i].x != 0.0f ? 1u : 0u) | (b[i].y != 0.0f ? 2u : 0u)
                   | (b[i].z != 0.0f ? 4u : 0u) | (b[i].w != 0.0f ? 8u : 0u);
        pY[wp * 4 + i][lane] = (unsigned char)m;
    }
    __syncthreads();

    int fgflag = 0;
    if (t < 128) {                      // assemble + store S words
        int rr = t >> 2, w = t & 3;
        unsigned v = nib_compress(*(const unsigned long long*)&pS[rr][w * 8]);
        gS[slice][10 + R0 + rr][1 + w] = v;
        fgflag = (v != 0u);
    } else {                            // assemble + store Y words
        int i = t - 128, rr = i >> 2, w = i & 3;
        gY[slice][R0 + rr][w] =
            nib_compress(*(const unsigned long long*)&pY[rr][w * 8]);
    }
    int anyfg = __syncthreads_or(fgflag);
    if (t == 0) gFG[blk] = anyfg;
}

// ---------------- kernel 2: bit-parallel walk + fused finalize ----------------
// combined(px) = dist to nearest opposite-valued pixel (s binary => one EDT
// term always zero), clamped at 10. Per offset (dr,dc) the opposite mask for
// 32 pixels is one xor of a funnel-shifted packed neighbor row, read straight
// from the L2-resident planes (guards baked in). Offset walk fully unrolled,
// batches of 4 d2-groups, one exit test per batch. found seeded with ~y_true;
// unfound pixels contribute exactly the clamp value 10.
__global__ __launch_bounds__(NT2)
void walk_kernel(float* __restrict__ out)
{
    __shared__ float wsum[4], wcnt[4];
    __shared__ int s_islast;
    __shared__ unsigned s_fgw[4];
    __shared__ int s_first[BB], s_last[BB];

    const int blk  = blockIdx.x;
    const int t    = threadIdx.x;
    const int lane = t & 31, wp = t >> 5;
    const int slice = blk >> 2;
    const int rem   = (blk & 3) * NT2 + t;     // 0..511 within slice
    const int r = rem >> 2, w = rem & 3;

    const unsigned* rowbase = &gS[slice][10 + r][0];
    const unsigned self = __ldg(rowbase + 1 + w);
    const unsigned ytm  = __ldg(&gY[slice][r][w]);
    unsigned found = ~ytm;                     // non-y_true pixels don't-care
    float sum = 0.0f;

    #pragma unroll
    for (int bi = 0; bi < NBATCH; ++bi) {
        unsigned gorv[4] = {0u, 0u, 0u, 0u};
        #pragma unroll
        for (int q = 0; q < 4; ++q) {
            const int gi = bi * 4 + q;
            if (gi < NG) {
                #pragma unroll
                for (int k = 0; k < TB.gcnt[gi]; ++k) {
                    const int dr = (int)TB.dr[TB.gstart[gi] + k];
                    const int dc = (int)TB.dc[TB.gstart[gi] + k];
                    const unsigned* rw = rowbase + dr * GSTR;
                    unsigned sh, valid;
                    if (dc >= 0) {
                        sh = __funnelshift_r(__ldg(rw + 1 + w), __ldg(rw + 2 + w), dc);
                        valid = (w == 3) ? (0xffffffffu >> dc) : 0xffffffffu;
                    } else {
                        const int kk = -dc;
                        sh = __funnelshift_l(__ldg(rw + w), __ldg(rw + 1 + w), kk);
                        valid = (w == 0) ? (0xffffffffu << kk) : 0xffffffffu;
                    }
                    unsigned rv = ((unsigned)(r + dr) < (unsigned)HH)
                                    ? 0xffffffffu : 0u;
                    gorv[q] |= (self ^ sh) & valid & rv;
                }
            }
        }
        #pragma unroll
        for (int q = 0; q < 4; ++q) {
            const int gi = bi * 4 + q;
            if (gi < NG) {
                unsigned nw = gorv[q] & ~found;       // fresh-per-group exact:
                sum += TB.sv[gi] * (float)__popc(nw); // found absorbs earlier
                found |= nw;
            }
        }
        if (found == 0xffffffffu) break;
    }
    sum += 10.0f * (float)__popc(~found);   // unfound => dist >= 10 => clamp
    float cntf = (float)__popc(ytm);

    // block reduction (4 warps)
    #pragma unroll
    for (int o = 16; o > 0; o >>= 1) {
        sum  += __shfl_down_sync(0xffffffffu, sum,  o);
        cntf += __shfl_down_sync(0xffffffffu, cntf, o);
    }
    if (lane == 0) { wsum[wp] = sum; wcnt[wp] = cntf; }
    __syncthreads();
    if (t == 0) {
        float s = wsum[0] + wsum[1] + wsum[2] + wsum[3];
        float c = wcnt[0] + wcnt[1] + wcnt[2] + wcnt[3];
        g_psum[blk] = s;
        g_pcnt[blk] = c;
        __threadfence();
        unsigned old = atomicAdd(&g_done, 1u);
        s_islast = (old == NBLK2 - 1u);
        if (s_islast) g_done = 0;   // self-reset for graph replay
    }
    __syncthreads();
    if (!s_islast) return;

    // fused finalize: per-batch fg slice range + masked sum
    __threadfence();
    int f = 0;
    if (t < NS) {
        #pragma unroll
        for (int q = 0; q < QPS; ++q) f |= gFG[QPS * t + q];
    }
    unsigned bal = __ballot_sync(0xffffffffu, f != 0);
    if (t < NS && lane == 0) s_fgw[wp] = bal;      // 4 warps cover t < 128
    __syncthreads();
    if (t < BB) {
        unsigned long long m = (unsigned long long)s_fgw[2 * t] |
                               ((unsigned long long)s_fgw[2 * t + 1] << 32);
        s_first[t] = m ? (__ffsll((long long)m) - 1) : 0;   // argmax(all-false)=0
        s_last[t]  = m ? (63 - __clzll((long long)m)) : (DD - 1);
    }
    __syncthreads();
    float ms = 0.0f, mc = 0.0f;
    #pragma unroll
    for (int q = 0; q < 4; ++q) {
        int p  = t + q * NT2;              // part index (NBLK2 = 512)
        int sl = p >> 2;
        int b  = sl >> 6, d = sl & (DD - 1);
        int in = (d >= s_first[b]) && (d <= s_last[b]);
        ms += in ? g_psum[p] : 0.0f;
        mc += g_pcnt[p];
    }
    #pragma unroll
    for (int o = 16; o > 0; o >>= 1) {
        ms += __shfl_down_sync(0xffffffffu, ms, o);
        mc += __shfl_down_sync(0xffffffffu, mc, o);
    }
    if (lane == 0) { wsum[wp] = ms; wcnt[wp] = mc; }
    __syncthreads();
    if (t == 0)
        out[0] = (wsum[0] + wsum[1] + wsum[2] + wsum[3]) /
                 (wcnt[0] + wcnt[1] + wcnt[2] + wcnt[3]);
}

extern "C" void kernel_launch(void* const* d_in, const int* in_sizes, int n_in,
                              void* d_out, int out_size)
{
    const float* yp = (const float*)d_in[0];
    const float* yt = (const float*)d_in[1];
    float* out = (float*)d_out;
    pack_kernel<<<NBLK1, NT1>>>(yp, yt);
    walk_kernel<<<NBLK2, NT2>>>(out);
}